// round 6
// baseline (speedup 1.0000x reference)
#include <cuda_runtime.h>
#include <cuda_fp16.h>

#define MAXN 100000
#define MAXE 1600000
#define HIDC 64
#define NB 64

// ---------------- device scratch ----------------
__device__ __align__(16) int    g_deg[MAXN];
__device__ __align__(16) int    g_off[MAXN + 1];
__device__ __align__(16) int    g_cur[MAXN];
__device__ __align__(16) int    g_srcidx[MAXE];
__device__ __align__(16) int    g_part[128];
__device__ __align__(16) __half2 g_y16a[MAXN * 32];
__device__ __align__(16) __half2 g_y16b[MAXN * 32];
__device__ __align__(16) float  g_agg[MAXN * HIDC];
__device__ __align__(16) float  g_hself[MAXN * HIDC];
__device__ __align__(16) float  g_stats[3 * 2 * HIDC];
__device__ float g_sumexp;
__device__ __align__(16) float  g_pool[NB * HIDC];
__device__ int   g_bcnt[NB];
__device__ int   g_is64;

// ---------------- f32x2 packed math helpers ----------------
__device__ __forceinline__ unsigned long long pack2(float lo, float hi) {
    unsigned long long r;
    asm("mov.b64 %0, {%1, %2};" : "=l"(r) : "f"(lo), "f"(hi));
    return r;
}
__device__ __forceinline__ void fma2(unsigned long long& d, unsigned long long a, unsigned long long b) {
    asm("fma.rn.f32x2 %0, %1, %2, %0;" : "+l"(d) : "l"(a), "l"(b));
}
__device__ __forceinline__ float2 unpack2(unsigned long long v) {
    float lo, hi;
    asm("mov.b64 {%0, %1}, %2;" : "=f"(lo), "=f"(hi) : "l"(v));
    return make_float2(lo, hi);
}

__device__ __forceinline__ int load_idx(const void* p, int i) {
    if (g_is64) return (int)((const long long*)p)[i];
    return ((const int*)p)[i];
}

// ---------------- 1: init (zero everything + dtype detect) ----------------
__global__ void k_init(const long long* __restrict__ ei, int n) {
    int i = blockIdx.x * blockDim.x + threadIdx.x;
    if (blockIdx.x == 0 && threadIdx.x < 32) {
        int lane = threadIdx.x;
        int bad = 0;
        for (int k = lane; k < 512; k += 32) {
            long long v = ei[k];
            bad |= (v < 0 || v >= (long long)n) ? 1 : 0;
        }
        bad = __any_sync(0xffffffffu, bad);
        if (lane == 0) g_is64 = bad ? 0 : 1;
    }
    if (i < n) g_deg[i] = 0;
    if (i < 3 * 2 * HIDC) g_stats[i] = 0.f;
    if (i < NB * HIDC) g_pool[i] = 0.f;
    if (i < NB) g_bcnt[i] = 0;
    if (i == 0) g_sumexp = 0.f;
}

// ---------------- 2: hist (+ fused prepool: sumexp + batch counts) ----------------
__global__ void k_hist(const void* __restrict__ ei, const float* __restrict__ x,
                       const void* __restrict__ batch, int e, int n) {
    __shared__ float ssum[256];
    __shared__ int hist[64];
    int tid = threadIdx.x;
    int i = blockIdx.x * 256 + tid;
    if (i < e) atomicAdd(&g_deg[load_idx(ei, e + i)], 1);
    if (tid < 64) hist[tid] = 0;
    __syncthreads();
    float loc = 0.f;
    if (i < n) {
        loc = expf(__ldg(&x[i * 6 + 4]));
        atomicAdd(&hist[load_idx(batch, i)], 1);
    }
    ssum[tid] = loc; __syncthreads();
    for (int d = 128; d > 0; d >>= 1) {
        if (tid < d) ssum[tid] += ssum[tid + d];
        __syncthreads();
    }
    if (tid == 0 && ssum[0] != 0.f) atomicAdd(&g_sumexp, ssum[0]);
    if (tid < 64 && hist[tid]) atomicAdd(&g_bcnt[tid], hist[tid]);
}

// ---------------- 3: scanA (per-block local exclusive scan + block totals) ----------------
__global__ void k_scanA(int n) {
    __shared__ int sh[1024];
    int t = threadIdx.x;
    int i = blockIdx.x * 1024 + t;
    int v = (i < n) ? g_deg[i] : 0;
    sh[t] = v; __syncthreads();
    for (int d = 1; d < 1024; d <<= 1) {
        int add = (t >= d) ? sh[t - d] : 0;
        __syncthreads();
        sh[t] += add;
        __syncthreads();
    }
    int excl = sh[t] - v;           // local exclusive prefix
    if (i < n) { g_off[i] = excl; g_cur[i] = excl; }
    if (t == 1023) g_part[blockIdx.x] = sh[1023];  // block total
}

// ---------------- 4: scatter (smem scan of block totals; scatter; absolutize g_off) ----------------
__global__ void k_scatter(const void* __restrict__ ei, int e, int n, int nb) {
    __shared__ int sp[128];
    int tid = threadIdx.x;
    if (tid < 128) sp[tid] = (tid < nb) ? g_part[tid] : 0;
    __syncthreads();
    // inclusive scan of 128
    for (int d = 1; d < 128; d <<= 1) {
        int v = 0;
        if (tid < 128 && tid >= d) v = sp[tid - d];
        __syncthreads();
        if (tid < 128) sp[tid] += v;
        __syncthreads();
    }
    // convert to exclusive
    int ex = 0;
    if (tid > 0 && tid < 128) ex = sp[tid - 1];
    __syncthreads();
    if (tid < 128) sp[tid] = ex;
    __syncthreads();

    int i = blockIdx.x * 256 + tid;
    if (i < e) {
        int src = load_idx(ei, i);
        int dst = load_idx(ei, e + i);
        int pos = atomicAdd(&g_cur[dst], 1) + sp[dst >> 10];
        g_srcidx[pos] = src;
    }
    if (i < n) g_off[i] += sp[i >> 10];   // local -> absolute
    if (i == 0) g_off[n] = e;
}

// ---------------- 5: fused layer-1 (agg over 6ch + mm + stats, fp16 out) ----------------
__global__ void __launch_bounds__(256)
k_l1(const float* __restrict__ x,
     const float* __restrict__ W1l, const float* __restrict__ W1r,
     const float* __restrict__ b1,
     __half2* __restrict__ yout, float* __restrict__ stats, int n) {
    __shared__ float sWl[6 * 64];
    __shared__ float sWr[6 * 64];
    __shared__ float sb[64];
    __shared__ float redS[8][64];
    __shared__ float redQ[8][64];
    int tid = threadIdx.x;
    for (int i = tid; i < 6 * 64; i += 256) { sWl[i] = W1l[i]; sWr[i] = W1r[i]; }
    if (tid < 64) sb[tid] = b1[tid];
    __syncthreads();

    int warp = tid >> 5, lane = tid & 31, c0 = lane * 2;
    int base = (blockIdx.x * 8 + warp) * 8;
    float ls0 = 0.f, ls1 = 0.f, lq0 = 0.f, lq1 = 0.f;

#pragma unroll 1
    for (int j = 0; j < 8; j++) {
        int node = base + j;
        bool valid = node < n;
        float acc = 0.f, xv = 0.f;
        int deg = 0;
        if (valid) {
            int s = g_off[node], t = g_off[node + 1];
            deg = t - s;
            int e = s;
            for (; e + 4 <= t; e += 4) {
                int i0 = g_srcidx[e], i1 = g_srcidx[e + 1];
                int i2 = g_srcidx[e + 2], i3 = g_srcidx[e + 3];
                if (lane < 6) {
                    float a0 = __ldg(&x[i0 * 6 + lane]);
                    float a1 = __ldg(&x[i1 * 6 + lane]);
                    float a2 = __ldg(&x[i2 * 6 + lane]);
                    float a3 = __ldg(&x[i3 * 6 + lane]);
                    acc += (a0 + a1) + (a2 + a3);
                }
            }
            for (; e < t; e++) {
                if (lane < 6) acc += __ldg(&x[g_srcidx[e] * 6 + lane]);
            }
            if (lane < 6) xv = __ldg(&x[node * 6 + lane]);
        }
        acc *= 1.f / fmaxf((float)deg, 1.f);

        float y0 = sb[c0], y1 = sb[c0 + 1];
#pragma unroll
        for (int k = 0; k < 6; k++) {
            float ak = __shfl_sync(0xffffffffu, acc, k);
            float xk = __shfl_sync(0xffffffffu, xv, k);
            y0 += ak * sWl[k * 64 + c0]     + xk * sWr[k * 64 + c0];
            y1 += ak * sWl[k * 64 + c0 + 1] + xk * sWr[k * 64 + c0 + 1];
        }
        if (valid) {
            yout[node * 32 + lane] = __float22half2_rn(make_float2(y0, y1));
            ls0 += y0; lq0 += y0 * y0;
            ls1 += y1; lq1 += y1 * y1;
        }
    }
    redS[warp][c0] = ls0; redS[warp][c0 + 1] = ls1;
    redQ[warp][c0] = lq0; redQ[warp][c0 + 1] = lq1;
    __syncthreads();
    if (tid < 64) {
        float s = 0.f, q = 0.f;
#pragma unroll
        for (int w2 = 0; w2 < 8; w2++) { s += redS[w2][tid]; q += redQ[w2][tid]; }
        atomicAdd(&stats[tid], s);
        atomicAdd(&stats[64 + tid], q);
    }
}

// ---------------- 6/8: agg64h (fp16 gather + BN-on-read + BN'd self) ----------------
__global__ void k_agg64h(const __half2* __restrict__ yin,
                         const float* __restrict__ stats,
                         const float* __restrict__ gam, const float* __restrict__ bet,
                         float invn,
                         float* __restrict__ aggout, float* __restrict__ hselfout, int n) {
    __shared__ float ssc[64], ssh[64];
    int tid = threadIdx.x;
    if (tid < 64) {
        float mu = stats[tid] * invn;
        float var = stats[64 + tid] * invn - mu * mu;
        float rstd = rsqrtf(var + 1e-5f);
        float sc = rstd * gam[tid];
        ssc[tid] = sc;
        ssh[tid] = bet[tid] - mu * sc;
    }
    __syncthreads();
    int w = (blockIdx.x * blockDim.x + tid) >> 5;
    int lane = tid & 31;
    if (w >= n) return;
    float sc0 = ssc[lane * 2], sc1 = ssc[lane * 2 + 1];
    float sh0 = ssh[lane * 2], sh1 = ssh[lane * 2 + 1];
    int s = g_off[w], t = g_off[w + 1];
    float ax = 0.f, ay = 0.f;
    int e = s;
#define BNX(f) fmaxf(fmaf((f).x, sc0, sh0), 0.f)
#define BNY(f) fmaxf(fmaf((f).y, sc1, sh1), 0.f)
    for (; e + 8 <= t; e += 8) {
        int i0 = __ldg(&g_srcidx[e]);
        int i1 = __ldg(&g_srcidx[e + 1]);
        int i2 = __ldg(&g_srcidx[e + 2]);
        int i3 = __ldg(&g_srcidx[e + 3]);
        int i4 = __ldg(&g_srcidx[e + 4]);
        int i5 = __ldg(&g_srcidx[e + 5]);
        int i6 = __ldg(&g_srcidx[e + 6]);
        int i7 = __ldg(&g_srcidx[e + 7]);
        float2 f0 = __half22float2(__ldg(&yin[i0 * 32 + lane]));
        float2 f1 = __half22float2(__ldg(&yin[i1 * 32 + lane]));
        float2 f2 = __half22float2(__ldg(&yin[i2 * 32 + lane]));
        float2 f3 = __half22float2(__ldg(&yin[i3 * 32 + lane]));
        float2 f4 = __half22float2(__ldg(&yin[i4 * 32 + lane]));
        float2 f5 = __half22float2(__ldg(&yin[i5 * 32 + lane]));
        float2 f6 = __half22float2(__ldg(&yin[i6 * 32 + lane]));
        float2 f7 = __half22float2(__ldg(&yin[i7 * 32 + lane]));
        ax += ((BNX(f0) + BNX(f1)) + (BNX(f2) + BNX(f3)))
            + ((BNX(f4) + BNX(f5)) + (BNX(f6) + BNX(f7)));
        ay += ((BNY(f0) + BNY(f1)) + (BNY(f2) + BNY(f3)))
            + ((BNY(f4) + BNY(f5)) + (BNY(f6) + BNY(f7)));
    }
    for (; e < t; e++) {
        int i0 = __ldg(&g_srcidx[e]);
        float2 f = __half22float2(__ldg(&yin[i0 * 32 + lane]));
        ax += BNX(f); ay += BNY(f);
    }
#undef BNX
#undef BNY
    float inv = 1.f / fmaxf((float)(t - s), 1.f);
    ((float2*)aggout)[w * 32 + lane] = make_float2(ax * inv, ay * inv);
    float2 fs = __half22float2(__ldg(&yin[w * 32 + lane]));
    ((float2*)hselfout)[w * 32 + lane] =
        make_float2(fmaxf(fmaf(fs.x, sc0, sh0), 0.f), fmaxf(fmaf(fs.y, sc1, sh1), 0.f));
}

// ---------------- 7/9: dense matmul (FFMA2) + BN-stats, fp16 output ----------------
__global__ void __launch_bounds__(256)
k_mm(const float* __restrict__ aggin, const float* __restrict__ hin,
     const float* __restrict__ Wl, const float* __restrict__ Wr,
     const float* __restrict__ bias, __half2* __restrict__ yout,
     float* __restrict__ stats, int n) {
    __shared__ float sWl[64 * 64];
    __shared__ float sWr[64 * 64];
    __shared__ float sb[64];
    __shared__ float redS[8][64];
    __shared__ float redQ[8][64];
    int tid = threadIdx.x;
    for (int i = tid; i < 64 * 64; i += 256) {
        int k = i >> 6, c = i & 63;
        int dst = (((k >> 1) << 6) + c) * 2 + (k & 1);
        sWl[dst] = Wl[i]; sWr[dst] = Wr[i];
    }
    if (tid < 64) sb[tid] = bias[tid];
    __syncthreads();

    int warp = tid >> 5, lane = tid & 31;
    int c0 = lane * 2;
    int base = (blockIdx.x * 8 + warp) * 8;

    unsigned long long acc0[8], acc1[8];
#pragma unroll
    for (int j = 0; j < 8; j++) {
        acc0[j] = pack2(sb[c0], 0.f);
        acc1[j] = pack2(sb[c0 + 1], 0.f);
    }
#pragma unroll 4
    for (int k = 0; k < 64; k += 4) {
        float4 wl01 = *(float4*)&sWl[((k >> 1) * 64 + c0) * 2];
        float4 wl23 = *(float4*)&sWl[(((k >> 1) + 1) * 64 + c0) * 2];
        float4 wr01 = *(float4*)&sWr[((k >> 1) * 64 + c0) * 2];
        float4 wr23 = *(float4*)&sWr[(((k >> 1) + 1) * 64 + c0) * 2];
        unsigned long long pl0a = pack2(wl01.x, wl01.y);
        unsigned long long pl0b = pack2(wl01.z, wl01.w);
        unsigned long long pl1a = pack2(wl23.x, wl23.y);
        unsigned long long pl1b = pack2(wl23.z, wl23.w);
        unsigned long long pr0a = pack2(wr01.x, wr01.y);
        unsigned long long pr0b = pack2(wr01.z, wr01.w);
        unsigned long long pr1a = pack2(wr23.x, wr23.y);
        unsigned long long pr1b = pack2(wr23.z, wr23.w);
#pragma unroll
        for (int j = 0; j < 8; j++) {
            int node = base + j; if (node >= n) node = n - 1;
            float4 a = *(const float4*)&aggin[node * 64 + k];
            float4 h = *(const float4*)&hin[node * 64 + k];
            unsigned long long axy = pack2(a.x, a.y);
            unsigned long long azw = pack2(a.z, a.w);
            unsigned long long hxy = pack2(h.x, h.y);
            unsigned long long hzw = pack2(h.z, h.w);
            fma2(acc0[j], axy, pl0a);
            fma2(acc1[j], axy, pl0b);
            fma2(acc0[j], azw, pl1a);
            fma2(acc1[j], azw, pl1b);
            fma2(acc0[j], hxy, pr0a);
            fma2(acc1[j], hxy, pr0b);
            fma2(acc0[j], hzw, pr1a);
            fma2(acc1[j], hzw, pr1b);
        }
    }

    float ls0 = 0.f, ls1 = 0.f, lq0 = 0.f, lq1 = 0.f;
#pragma unroll
    for (int j = 0; j < 8; j++) {
        int node = base + j;
        if (node < n) {
            float2 u0 = unpack2(acc0[j]);
            float2 u1 = unpack2(acc1[j]);
            float v0 = u0.x + u0.y;
            float v1 = u1.x + u1.y;
            yout[node * 32 + lane] = __float22half2_rn(make_float2(v0, v1));
            ls0 += v0; lq0 += v0 * v0;
            ls1 += v1; lq1 += v1 * v1;
        }
    }
    redS[warp][c0] = ls0; redS[warp][c0 + 1] = ls1;
    redQ[warp][c0] = lq0; redQ[warp][c0 + 1] = lq1;
    __syncthreads();
    if (tid < 64) {
        float s = 0.f, q = 0.f;
#pragma unroll
        for (int w2 = 0; w2 < 8; w2++) { s += redS[w2][tid]; q += redQ[w2][tid]; }
        atomicAdd(&stats[tid], s);
        atomicAdd(&stats[64 + tid], q);
    }
}

// ---------------- 10: pooling (BN3 + ReLU on read) ----------------
__global__ void k_pool(const void* __restrict__ batch, const float* __restrict__ x,
                       const __half2* __restrict__ y16,
                       const float* __restrict__ stats,
                       const float* __restrict__ gam, const float* __restrict__ bet,
                       float invn, int n) {
    __shared__ float w[64];
    __shared__ int bb[64];
    __shared__ float2 sscsh[64];
    int tid = threadIdx.x;  // 0..31
    int base = blockIdx.x * 64;
    float S = g_sumexp;
    for (int j = tid; j < 64; j += 32) {
        int i = base + j;
        if (i < n) { w[j] = expf(__ldg(&x[i * 6 + 4])) / S; bb[j] = load_idx(batch, i); }
        else { w[j] = 0.f; bb[j] = -1; }
        float mu = stats[j] * invn;
        float var = stats[64 + j] * invn - mu * mu;
        float rstd = rsqrtf(var + 1e-5f);
        float sc = rstd * gam[j];
        sscsh[j] = make_float2(sc, bet[j] - mu * sc);
    }
    __syncthreads();
    int c0 = tid * 2;
    float2 p0 = sscsh[c0], p1 = sscsh[c0 + 1];
    int m = n - base; if (m > 64) m = 64;
#define BNV(f) make_float2(fmaxf(fmaf((f).x, p0.x, p0.y), 0.f), fmaxf(fmaf((f).y, p1.x, p1.y), 0.f))
    if (m == 64 && bb[0] == bb[63]) {
        float ax0 = 0.f, ay0 = 0.f, ax1 = 0.f, ay1 = 0.f;
        float ax2 = 0.f, ay2 = 0.f, ax3 = 0.f, ay3 = 0.f;
        for (int j = 0; j < 64; j += 4) {
            float2 f0 = BNV(__half22float2(__ldg(&y16[(base + j + 0) * 32 + tid])));
            float2 f1 = BNV(__half22float2(__ldg(&y16[(base + j + 1) * 32 + tid])));
            float2 f2 = BNV(__half22float2(__ldg(&y16[(base + j + 2) * 32 + tid])));
            float2 f3 = BNV(__half22float2(__ldg(&y16[(base + j + 3) * 32 + tid])));
            ax0 += w[j] * f0.x;     ay0 += w[j] * f0.y;
            ax1 += w[j + 1] * f1.x; ay1 += w[j + 1] * f1.y;
            ax2 += w[j + 2] * f2.x; ay2 += w[j + 2] * f2.y;
            ax3 += w[j + 3] * f3.x; ay3 += w[j + 3] * f3.y;
        }
        atomicAdd(&g_pool[bb[0] * 64 + c0],     (ax0 + ax1) + (ax2 + ax3));
        atomicAdd(&g_pool[bb[0] * 64 + c0 + 1], (ay0 + ay1) + (ay2 + ay3));
    } else {
        float accx = 0.f, accy = 0.f;
        int cur = bb[0];
        for (int j = 0; j < m; j++) {
            int b = bb[j];
            if (b != cur) {
                if (cur >= 0) {
                    atomicAdd(&g_pool[cur * 64 + c0], accx);
                    atomicAdd(&g_pool[cur * 64 + c0 + 1], accy);
                }
                accx = 0.f; accy = 0.f; cur = b;
            }
            float2 f = BNV(__half22float2(__ldg(&y16[(base + j) * 32 + tid])));
            accx += w[j] * f.x; accy += w[j] * f.y;
        }
        if (cur >= 0 && m > 0) {
            atomicAdd(&g_pool[cur * 64 + c0], accx);
            atomicAdd(&g_pool[cur * 64 + c0 + 1], accy);
        }
    }
#undef BNV
}

// ---------------- 11: heads ----------------
__global__ void k_head(const float* __restrict__ phW1, const float* __restrict__ phb1,
                       const float* __restrict__ phW2, const float* __restrict__ phb2,
                       const float* __restrict__ trW1, const float* __restrict__ trb1,
                       const float* __restrict__ trW2, const float* __restrict__ trb2,
                       float* __restrict__ out) {
    __shared__ float pool[64 * 64];
    __shared__ float hid[64 * 32];
    __shared__ float hidt[64 * 16];
    int tid = threadIdx.x;
    for (int i = tid; i < 64 * 64; i += 256) {
        int b = i >> 6;
        float c = (float)g_bcnt[b];
        pool[i] = g_pool[i] / fmaxf(c, 1.f);
    }
    __syncthreads();
    for (int i = tid; i < 64 * 32; i += 256) {
        int b = i >> 5, j = i & 31;
        float s = phb1[j];
        for (int k = 0; k < 64; k++) s += pool[b * 64 + k] * phW1[k * 32 + j];
        hid[i] = fmaxf(s, 0.f);
    }
    for (int i = tid; i < 64 * 16; i += 256) {
        int b = i >> 4, j = i & 15;
        float s = trb1[j];
        for (int k = 0; k < 64; k++) s += pool[b * 64 + k] * trW1[k * 16 + j];
        hidt[i] = fmaxf(s, 0.f);
    }
    __syncthreads();
    for (int i = tid; i < 64 * 3; i += 256) {
        int b = i / 3, j = i - b * 3;
        float s = phb2[j];
        for (int k = 0; k < 32; k++) s += hid[b * 32 + k] * phW2[k * 3 + j];
        out[i] = s;
    }
    for (int i = tid; i < 64; i += 256) {
        float s = trb2[0];
        for (int k = 0; k < 16; k++) s += hidt[i * 16 + k] * trW2[k];
        out[192 + i] = 1.f / (1.f + expf(-s));
    }
}

// ---------------- launch ----------------
extern "C" void kernel_launch(void* const* d_in, const int* in_sizes, int n_in,
                              void* d_out, int out_size) {
    const float* x   = (const float*)d_in[0];
    const void*  ei  = d_in[1];
    const void*  bat = d_in[2];
    const float* W1l = (const float*)d_in[3];
    const float* b1  = (const float*)d_in[4];
    const float* W1r = (const float*)d_in[5];
    const float* W2l = (const float*)d_in[6];
    const float* b2  = (const float*)d_in[7];
    const float* W2r = (const float*)d_in[8];
    const float* W3l = (const float*)d_in[9];
    const float* b3  = (const float*)d_in[10];
    const float* W3r = (const float*)d_in[11];
    const float* g1  = (const float*)d_in[12];
    const float* be1 = (const float*)d_in[13];
    const float* g2  = (const float*)d_in[14];
    const float* be2 = (const float*)d_in[15];
    const float* g3  = (const float*)d_in[16];
    const float* be3 = (const float*)d_in[17];
    const float* phW1 = (const float*)d_in[18];
    const float* phb1 = (const float*)d_in[19];
    const float* phW2 = (const float*)d_in[20];
    const float* phb2 = (const float*)d_in[21];
    const float* trW1 = (const float*)d_in[22];
    const float* trb1 = (const float*)d_in[23];
    const float* trW2 = (const float*)d_in[24];
    const float* trb2 = (const float*)d_in[25];
    float* out = (float*)d_out;

    int n = in_sizes[0] / 6;
    int e = in_sizes[1] / 2;

    float *p_agg, *p_hself, *p_stats;
    __half2 *p_ya, *p_yb;
    cudaGetSymbolAddress((void**)&p_agg, g_agg);
    cudaGetSymbolAddress((void**)&p_hself, g_hself);
    cudaGetSymbolAddress((void**)&p_stats, g_stats);
    cudaGetSymbolAddress((void**)&p_ya, g_y16a);
    cudaGetSymbolAddress((void**)&p_yb, g_y16b);

    int nb = (n + 1023) / 1024;
    int eBlocks = (e + 255) / 256;
    int aggBlocks = (n * 32 + 255) / 256;
    int mmBlocks = (n + 63) / 64;
    float invn = 1.f / (float)n;

    // 1-4: init + CSR
    k_init<<<(n + 255) / 256, 256>>>((const long long*)ei, n);
    k_hist<<<eBlocks, 256>>>(ei, x, bat, e, n);
    k_scanA<<<nb, 1024>>>(n);
    k_scatter<<<eBlocks, 256>>>(ei, e, n, nb);   // launch #4 -> profiled

    // 5: fused layer 1
    k_l1<<<mmBlocks, 256>>>(x, W1l, W1r, b1, p_ya, p_stats + 0 * 128, n);

    // 6-7: layer 2
    k_agg64h<<<aggBlocks, 256>>>(p_ya, p_stats + 0 * 128, g1, be1, invn, p_agg, p_hself, n);
    k_mm<<<mmBlocks, 256>>>(p_agg, p_hself, W2l, W2r, b2, p_yb, p_stats + 1 * 128, n);

    // 8-9: layer 3
    k_agg64h<<<aggBlocks, 256>>>(p_yb, p_stats + 1 * 128, g2, be2, invn, p_agg, p_hself, n);
    k_mm<<<mmBlocks, 256>>>(p_agg, p_hself, W3l, W3r, b3, p_ya, p_stats + 2 * 128, n);

    // 10-11: pooling + heads
    k_pool<<<mmBlocks, 32>>>(bat, x, p_ya, p_stats + 2 * 128, g3, be3, invn, n);
    k_head<<<1, 256>>>(phW1, phb1, phW2, phb2, trW1, trb1, trW2, trb2, out);
}